// round 10
// baseline (speedup 1.0000x reference)
#include <cuda_runtime.h>
#include <cstdint>
#include <math.h>

// ============================================================================
// get_model_pred — tf32 mma.sync, warp tile 64x64, 2-stage cp.async ring,
// 3 CTAs/SM (launch_bounds 128,3; smem 71.7KB/CTA) for 3 warps/SMSP.
//   edge_embed = relu(pred@We1+b1)@We2+b2
//   head       = softmax(relu(edge@Wt1+bt1)@Wt2+bt2) ; stack ; gate
// Outputs: types_w(4,E) | multiW(4,E) | type_output(E,4) | edge_embed(E,512)
// ============================================================================

#define D 512
#define E_MAX 89700

__device__ float g_h  [(size_t)E_MAX * D];   // tf32-rounded hidden
__device__ float g_W1r[D * D];
__device__ float g_W2r[D * D];
__device__ float g_Wt1r[D * 128];

// SMEM: As [128][36] (pad 4), Bs [32][136] (pad 8) — conflict-free walks
#define AS_STRIDE 36
#define BS_STRIDE 136
#define AS_BYTES (128 * AS_STRIDE * 4)          // 18432
#define BS_BYTES (32 * BS_STRIDE * 4)           // 17408
#define STAGE_BYTES (AS_BYTES + BS_BYTES)       // 35840
#define SMEM_TOTAL (2 * STAGE_BYTES)            // 71680
#define NTH 128                                 // 4 warps per CTA

__device__ __forceinline__ uint32_t smem_u32(const void* p) {
    uint32_t a;
    asm("{ .reg .u64 t; cvta.to.shared.u64 t, %1; cvt.u32.u64 %0, t; }"
        : "=r"(a) : "l"(p));
    return a;
}
__device__ __forceinline__ uint32_t f2tf(float x) {   // round-to-nearest tf32
    uint32_t u;
    asm("cvt.rna.tf32.f32 %0, %1;" : "=r"(u) : "f"(x));
    return u;
}
__device__ __forceinline__ float rna_tf32f(float x) { return __uint_as_float(f2tf(x)); }
__device__ __forceinline__ float gatef(float p) {
    const float BEL = 0.025f;
    const float HI  = 1.0f / 2.2f + 0.025f;
    return (p <= BEL) ? 0.0f : ((p >= HI) ? 1.0f : 2.2f * (p - BEL));
}
__device__ __forceinline__ void cpa16(uint32_t dst, const void* src, bool valid) {
    int sz = valid ? 16 : 0;
    asm volatile("cp.async.cg.shared.global [%0], [%1], 16, %2;"
                 :: "r"(dst), "l"(src), "r"(sz) : "memory");
}
#define CP_COMMIT() asm volatile("cp.async.commit_group;" ::: "memory")
#define CP_WAIT(n)  asm volatile("cp.async.wait_group %0;" :: "n"(n) : "memory")

__device__ __forceinline__ void mma_tf32(float& d0, float& d1, float& d2, float& d3,
                                         uint32_t a0, uint32_t a1, uint32_t a2, uint32_t a3,
                                         uint32_t b0, uint32_t b1) {
    asm volatile(
        "mma.sync.aligned.m16n8k8.row.col.f32.tf32.tf32.f32 "
        "{%0,%1,%2,%3}, {%4,%5,%6,%7}, {%8,%9}, {%0,%1,%2,%3};"
        : "+f"(d0), "+f"(d1), "+f"(d2), "+f"(d3)
        : "r"(a0), "r"(a1), "r"(a2), "r"(a3), "r"(b0), "r"(b1));
}

// ---------------------------------------------------------------------------
// Prep: tf32-round the three weight matrices (pred rounding fused in gemm1)
// ---------------------------------------------------------------------------
__global__ void round_weights(const float4* __restrict__ W1, const float4* __restrict__ W2,
                              const float4* __restrict__ Wt1, float4* __restrict__ o1,
                              float4* __restrict__ o2, float4* __restrict__ o3) {
    int i = blockIdx.x * blockDim.x + threadIdx.x;
    const float4* src; float4* dst; int j;
    if (i < 65536)        { src = W1;  dst = o1; j = i; }
    else if (i < 131072)  { src = W2;  dst = o2; j = i - 65536; }
    else if (i < 147456)  { src = Wt1; dst = o3; j = i - 131072; }
    else return;
    float4 v = src[j];
    dst[j] = make_float4(rna_tf32f(v.x), rna_tf32f(v.y), rna_tf32f(v.z), rna_tf32f(v.w));
}

// ---------------------------------------------------------------------------
// Stage loader, 128 threads. A: (E x D) row-major; B: (D x NW) row-major.
// ---------------------------------------------------------------------------
template <int NW>
__device__ __forceinline__ void load_tile(
    uint32_t sA, uint32_t sB, const float* __restrict__ Ag,
    const float* __restrict__ Bg, int rowBase, int colBase, int kb, int E, int tid)
{
#pragma unroll
    for (int i = 0; i < 8; i++) {
        int idx = i * NTH + tid;
        int row = idx >> 3, f4 = (idx & 7) << 2;
        bool v = (rowBase + row) < E;
        const float* src = Ag + (size_t)(rowBase + row) * D + kb + f4;
        cpa16(sA + (uint32_t)(row * AS_STRIDE + f4) * 4, v ? src : Ag, v);
    }
#pragma unroll
    for (int i = 0; i < 8; i++) {
        int idx = i * NTH + tid;
        int k = idx >> 5, f4 = (idx & 31) << 2;
        const float* src = Bg + (size_t)(kb + k) * NW + colBase + f4;
        cpa16(sB + (uint32_t)(k * BS_STRIDE + f4) * 4, src, true);
    }
}

// ---------------------------------------------------------------------------
// Warp 64x64 compute on one 32-deep K chunk. acc[4 m-tiles][8 n-tiles][4].
// ---------------------------------------------------------------------------
template <bool CVTA>
__device__ __forceinline__ void compute_tile6464(
    const float* As, const float* Bs, float acc[4][8][4],
    int wm, int wn, int gid, int tig)
{
    const uint32_t* Au = (const uint32_t*)As;
    const uint32_t* Bu = (const uint32_t*)Bs;
#pragma unroll
    for (int ks = 0; ks < 4; ks++) {
        const int k = ks * 8 + tig;
        uint32_t a[4][4], b[8][2];
#pragma unroll
        for (int mt = 0; mt < 4; mt++) {
            const int m = wm * 64 + mt * 16 + gid;
            if (CVTA) {
                a[mt][0] = f2tf(As[m * AS_STRIDE + k]);
                a[mt][1] = f2tf(As[(m + 8) * AS_STRIDE + k]);
                a[mt][2] = f2tf(As[m * AS_STRIDE + k + 4]);
                a[mt][3] = f2tf(As[(m + 8) * AS_STRIDE + k + 4]);
            } else {
                a[mt][0] = Au[m * AS_STRIDE + k];
                a[mt][1] = Au[(m + 8) * AS_STRIDE + k];
                a[mt][2] = Au[m * AS_STRIDE + k + 4];
                a[mt][3] = Au[(m + 8) * AS_STRIDE + k + 4];
            }
        }
#pragma unroll
        for (int nt = 0; nt < 8; nt++) {
            const int n = wn * 64 + nt * 8 + gid;
            b[nt][0] = Bu[k * BS_STRIDE + n];
            b[nt][1] = Bu[(k + 4) * BS_STRIDE + n];
        }
#pragma unroll
        for (int mt = 0; mt < 4; mt++)
#pragma unroll
            for (int nt = 0; nt < 8; nt++)
                mma_tf32(acc[mt][nt][0], acc[mt][nt][1], acc[mt][nt][2], acc[mt][nt][3],
                         a[mt][0], a[mt][1], a[mt][2], a[mt][3],
                         b[nt][0], b[nt][1]);
    }
}

// 2-stage pipelined mainloop (K = 512, 16 chunks of 32).
// iter kt: wait for chunk kt, compute stage kt&1, then reload that stage
// with chunk kt+2 (sync before reload guarantees all warps finished reading).
template <int NW, bool CVTA>
__device__ __forceinline__ void gemm_mainloop(
    char* smem, const float* __restrict__ Ag, const float* __restrict__ Bg,
    int rowBase, int colBase, int E, int tid, float acc[4][8][4],
    int wm, int wn, int gid, int tig)
{
    const uint32_t sb = smem_u32(smem);

#pragma unroll
    for (int mt = 0; mt < 4; mt++)
#pragma unroll
        for (int nt = 0; nt < 8; nt++)
#pragma unroll
            for (int r = 0; r < 4; r++) acc[mt][nt][r] = 0.0f;

    load_tile<NW>(sb, sb + AS_BYTES, Ag, Bg, rowBase, colBase, 0, E, tid);
    CP_COMMIT();
    load_tile<NW>(sb + STAGE_BYTES, sb + STAGE_BYTES + AS_BYTES,
                  Ag, Bg, rowBase, colBase, 32, E, tid);
    CP_COMMIT();

    for (int kt = 0; kt < 16; kt++) {
        CP_WAIT(1);
        __syncthreads();
        const uint32_t st = sb + (uint32_t)(kt & 1) * STAGE_BYTES;
        const float* As = (const float*)(smem + (kt & 1) * STAGE_BYTES);
        const float* Bs = As + 128 * AS_STRIDE;
        compute_tile6464<CVTA>(As, Bs, acc, wm, wn, gid, tig);
        __syncthreads();
        if (kt + 2 < 16)
            load_tile<NW>(st, st + AS_BYTES, Ag, Bg, rowBase, colBase,
                          (kt + 2) * 32, E, tid);
        CP_COMMIT();
    }
    CP_WAIT(0);
    __syncthreads();
}

// ---------------------------------------------------------------------------
// Big GEMM: C(E x 512) = A @ B(512x512) + bias. CTA 128x128, 128 thr,
// 3 CTAs/SM. Grid (4, rb): col block fastest -> A rows shared via L2.
// ---------------------------------------------------------------------------
template <bool CVTA, bool RELU_ROUND>
__global__ __launch_bounds__(NTH, 3) void gemm_mma(
    const float* __restrict__ Ag, const float* __restrict__ Bg,
    const float* __restrict__ bias, float* __restrict__ C, int E)
{
    extern __shared__ __align__(16) char smem[];
    __shared__ float sbias[128];

    const int tid = threadIdx.x;
    const int wid = tid >> 5, lane = tid & 31;
    const int wm = wid >> 1, wn = wid & 1;       // 2x2 warp grid, warp 64x64
    const int gid = lane >> 2, tig = lane & 3;
    const int rowBase = blockIdx.y * 128;
    const int colBase = blockIdx.x * 128;

    sbias[tid] = bias[colBase + tid];

    float acc[4][8][4];
    gemm_mainloop<D, CVTA>(smem, Ag, Bg, rowBase, colBase, E, tid, acc,
                           wm, wn, gid, tig);

#pragma unroll
    for (int mt = 0; mt < 4; mt++) {
        const int r0 = rowBase + wm * 64 + mt * 16 + gid;
#pragma unroll
        for (int nt = 0; nt < 8; nt++) {
            const int cl = wn * 64 + nt * 8 + tig * 2;
            const int c = colBase + cl;
            float v0 = acc[mt][nt][0] + sbias[cl];
            float v1 = acc[mt][nt][1] + sbias[cl + 1];
            float v2 = acc[mt][nt][2] + sbias[cl];
            float v3 = acc[mt][nt][3] + sbias[cl + 1];
            if (RELU_ROUND) {
                v0 = rna_tf32f(fmaxf(v0, 0.f)); v1 = rna_tf32f(fmaxf(v1, 0.f));
                v2 = rna_tf32f(fmaxf(v2, 0.f)); v3 = rna_tf32f(fmaxf(v3, 0.f));
            }
            if (r0 < E)     *(float2*)&C[(size_t)r0 * D + c]       = make_float2(v0, v1);
            if (r0 + 8 < E) *(float2*)&C[(size_t)(r0 + 8) * D + c] = make_float2(v2, v3);
        }
    }
}

// ---------------------------------------------------------------------------
// Head: T1 = relu(edge @ Wt1 + bt1) (128x128, K=512), same warp structure,
// then per-row 128->4 GEMV + softmax + gate + small outputs.
// ---------------------------------------------------------------------------
__global__ __launch_bounds__(NTH, 3) void head_mma(
    const float* __restrict__ EE, const float* __restrict__ Wt1,
    const float* __restrict__ bt1, const float* __restrict__ Wt2,
    const float* __restrict__ bt2, float* __restrict__ out, int E)
{
    extern __shared__ __align__(16) char smem[];
    __shared__ float sWt2[512];
    __shared__ float sbt1[128];

    const int tid = threadIdx.x;
    const int wid = tid >> 5, lane = tid & 31;
    const int wm = wid >> 1, wn = wid & 1;
    const int gid = lane >> 2, tig = lane & 3;
    const int rowBase = blockIdx.x * 128;

    sbt1[tid] = bt1[tid];
    sWt2[tid]       = Wt2[tid];
    sWt2[tid + 128] = Wt2[tid + 128];
    sWt2[tid + 256] = Wt2[tid + 256];
    sWt2[tid + 384] = Wt2[tid + 384];

    float acc[4][8][4];
    gemm_mainloop<128, true>(smem, EE, Wt1, rowBase, 0, E, tid, acc,
                             wm, wn, gid, tig);

    // T1 -> padded slab [128][129] (66048 B <= 71680 B smem)
    float* T1 = (float*)smem;
#pragma unroll
    for (int mt = 0; mt < 4; mt++) {
        const int r = wm * 64 + mt * 16 + gid;
#pragma unroll
        for (int nt = 0; nt < 8; nt++) {
            const int c = wn * 64 + nt * 8 + tig * 2;
            T1[r * 129 + c]           = fmaxf(acc[mt][nt][0] + sbt1[c], 0.f);
            T1[r * 129 + c + 1]       = fmaxf(acc[mt][nt][1] + sbt1[c + 1], 0.f);
            T1[(r + 8) * 129 + c]     = fmaxf(acc[mt][nt][2] + sbt1[c], 0.f);
            T1[(r + 8) * 129 + c + 1] = fmaxf(acc[mt][nt][3] + sbt1[c + 1], 0.f);
        }
    }
    __syncthreads();

    // Phase 2: one thread per row (128 threads = 128 rows)
    {
        const int gr = rowBase + tid;
        if (gr < E) {
            float t0 = __ldg(&bt2[0]), t1 = __ldg(&bt2[1]);
            float t2 = __ldg(&bt2[2]), t3 = __ldg(&bt2[3]);
            const float* rp = T1 + tid * 129;
#pragma unroll 8
            for (int k = 0; k < 128; k++) {
                float x = rp[k];
                t0 = fmaf(x, sWt2[k * 4 + 0], t0);
                t1 = fmaf(x, sWt2[k * 4 + 1], t1);
                t2 = fmaf(x, sWt2[k * 4 + 2], t2);
                t3 = fmaf(x, sWt2[k * 4 + 3], t3);
            }
            float m = fmaxf(fmaxf(t0, t1), fmaxf(t2, t3));
            float e0 = __expf(t0 - m), e1 = __expf(t1 - m);
            float e2 = __expf(t2 - m), e3 = __expf(t3 - m);
            float inv = 1.0f / (e0 + e1 + e2 + e3);
            float p0 = e0 * inv, p1 = e1 * inv, p2 = e2 * inv, p3 = e3 * inv;
            float tw0 = 1.0f - p0;

            const size_t Es = (size_t)E;
            out[0 * Es + gr] = tw0;
            out[1 * Es + gr] = p1;
            out[2 * Es + gr] = p2;
            out[3 * Es + gr] = p3;
            float* mw = out + 4 * Es;
            mw[0 * Es + gr] = gatef(tw0);
            mw[1 * Es + gr] = gatef(p1);
            mw[2 * Es + gr] = gatef(p2);
            mw[3 * Es + gr] = gatef(p3);
            float* to = out + 8 * Es;
            to[(size_t)gr * 4 + 0] = p0;
            to[(size_t)gr * 4 + 1] = p1;
            to[(size_t)gr * 4 + 2] = p2;
            to[(size_t)gr * 4 + 3] = p3;
        }
    }
}

// ---------------------------------------------------------------------------
extern "C" void kernel_launch(void* const* d_in, const int* in_sizes, int n_in,
                              void* d_out, int out_size)
{
    const float* pred = (const float*)d_in[1];
    const float* We1  = (const float*)d_in[2];
    const float* be1  = (const float*)d_in[3];
    const float* We2  = (const float*)d_in[4];
    const float* be2  = (const float*)d_in[5];
    const float* Wt1  = (const float*)d_in[6];
    const float* bt1  = (const float*)d_in[7];
    const float* Wt2  = (const float*)d_in[8];
    const float* bt2  = (const float*)d_in[9];

    const int E = in_sizes[1] / D;
    float* out  = (float*)d_out;
    float* edge = out + (size_t)12 * E;

    float *pH, *pW1r, *pW2r, *pWt1r;
    cudaGetSymbolAddress((void**)&pH,   g_h);
    cudaGetSymbolAddress((void**)&pW1r, g_W1r);
    cudaGetSymbolAddress((void**)&pW2r, g_W2r);
    cudaGetSymbolAddress((void**)&pWt1r, g_Wt1r);

    cudaFuncSetAttribute(gemm_mma<true, true>,
                         cudaFuncAttributeMaxDynamicSharedMemorySize, SMEM_TOTAL);
    cudaFuncSetAttribute(gemm_mma<false, false>,
                         cudaFuncAttributeMaxDynamicSharedMemorySize, SMEM_TOTAL);
    cudaFuncSetAttribute(head_mma,
                         cudaFuncAttributeMaxDynamicSharedMemorySize, SMEM_TOTAL);

    round_weights<<<(147456 + 255) / 256, 256>>>(
        (const float4*)We1, (const float4*)We2, (const float4*)Wt1,
        (float4*)pW1r, (float4*)pW2r, (float4*)pWt1r);

    const int rb = (E + 127) / 128;
    dim3 grid(4, rb);   // col block fastest -> A shared via L2

    gemm_mma<true,  true ><<<grid, NTH, SMEM_TOTAL>>>(pred, pW1r, be1, pH, E);
    gemm_mma<false, false><<<grid, NTH, SMEM_TOTAL>>>(pH,   pW2r, be2, edge, E);
    head_mma<<<rb, NTH, SMEM_TOTAL>>>(edge, pWt1r, bt1, Wt2, bt2, out, E);
}

// round 11
// speedup vs baseline: 1.1029x; 1.1029x over previous
#include <cuda_runtime.h>
#include <cstdint>
#include <math.h>

// ============================================================================
// get_model_pred — tf32 mma.sync, warp tile 64x64, 3-stage cp.async ring,
// single-barrier pipeline + fragment double-buffering.
//   edge_embed = relu(pred@We1+b1)@We2+b2
//   head       = softmax(relu(edge@Wt1+bt1)@Wt2+bt2) ; stack ; gate
// Outputs: types_w(4,E) | multiW(4,E) | type_output(E,4) | edge_embed(E,512)
// ============================================================================

#define D 512
#define E_MAX 89700

__device__ float g_h  [(size_t)E_MAX * D];   // tf32-rounded hidden
__device__ float g_W1r[D * D];
__device__ float g_W2r[D * D];
__device__ float g_Wt1r[D * 128];

// SMEM: As [128][36] (pad 4), Bs [32][136] (pad 8) — conflict-free walks
#define AS_STRIDE 36
#define BS_STRIDE 136
#define AS_BYTES (128 * AS_STRIDE * 4)          // 18432
#define BS_BYTES (32 * BS_STRIDE * 4)           // 17408
#define STAGE_BYTES (AS_BYTES + BS_BYTES)       // 35840
#define SMEM_TOTAL (3 * STAGE_BYTES)            // 107520 -> 2 CTA/SM
#define NTH 128                                 // 4 warps per CTA

__device__ __forceinline__ uint32_t smem_u32(const void* p) {
    uint32_t a;
    asm("{ .reg .u64 t; cvta.to.shared.u64 t, %1; cvt.u32.u64 %0, t; }"
        : "=r"(a) : "l"(p));
    return a;
}
__device__ __forceinline__ uint32_t f2tf(float x) {   // round-to-nearest tf32
    uint32_t u;
    asm("cvt.rna.tf32.f32 %0, %1;" : "=r"(u) : "f"(x));
    return u;
}
__device__ __forceinline__ float rna_tf32f(float x) { return __uint_as_float(f2tf(x)); }
__device__ __forceinline__ float gatef(float p) {
    const float BEL = 0.025f;
    const float HI  = 1.0f / 2.2f + 0.025f;
    return (p <= BEL) ? 0.0f : ((p >= HI) ? 1.0f : 2.2f * (p - BEL));
}
__device__ __forceinline__ void cpa16(uint32_t dst, const void* src, bool valid) {
    int sz = valid ? 16 : 0;
    asm volatile("cp.async.cg.shared.global [%0], [%1], 16, %2;"
                 :: "r"(dst), "l"(src), "r"(sz) : "memory");
}
#define CP_COMMIT() asm volatile("cp.async.commit_group;" ::: "memory")
#define CP_WAIT(n)  asm volatile("cp.async.wait_group %0;" :: "n"(n) : "memory")

__device__ __forceinline__ void mma_tf32(float& d0, float& d1, float& d2, float& d3,
                                         uint32_t a0, uint32_t a1, uint32_t a2, uint32_t a3,
                                         uint32_t b0, uint32_t b1) {
    asm volatile(
        "mma.sync.aligned.m16n8k8.row.col.f32.tf32.tf32.f32 "
        "{%0,%1,%2,%3}, {%4,%5,%6,%7}, {%8,%9}, {%0,%1,%2,%3};"
        : "+f"(d0), "+f"(d1), "+f"(d2), "+f"(d3)
        : "r"(a0), "r"(a1), "r"(a2), "r"(a3), "r"(b0), "r"(b1));
}

// ---------------------------------------------------------------------------
// Prep: tf32-round the three weight matrices (pred rounding fused in gemm1)
// ---------------------------------------------------------------------------
__global__ void round_weights(const float4* __restrict__ W1, const float4* __restrict__ W2,
                              const float4* __restrict__ Wt1, float4* __restrict__ o1,
                              float4* __restrict__ o2, float4* __restrict__ o3) {
    int i = blockIdx.x * blockDim.x + threadIdx.x;
    const float4* src; float4* dst; int j;
    if (i < 65536)        { src = W1;  dst = o1; j = i; }
    else if (i < 131072)  { src = W2;  dst = o2; j = i - 65536; }
    else if (i < 147456)  { src = Wt1; dst = o3; j = i - 131072; }
    else return;
    float4 v = src[j];
    dst[j] = make_float4(rna_tf32f(v.x), rna_tf32f(v.y), rna_tf32f(v.z), rna_tf32f(v.w));
}

// ---------------------------------------------------------------------------
// Stage loader, 128 threads. A: (E x D) row-major; B: (D x NW) row-major.
// ---------------------------------------------------------------------------
template <int NW>
__device__ __forceinline__ void load_tile(
    uint32_t sA, uint32_t sB, const float* __restrict__ Ag,
    const float* __restrict__ Bg, int rowBase, int colBase, int kb, int E, int tid)
{
#pragma unroll
    for (int i = 0; i < 8; i++) {
        int idx = i * NTH + tid;
        int row = idx >> 3, f4 = (idx & 7) << 2;
        bool v = (rowBase + row) < E;
        const float* src = Ag + (size_t)(rowBase + row) * D + kb + f4;
        cpa16(sA + (uint32_t)(row * AS_STRIDE + f4) * 4, v ? src : Ag, v);
    }
#pragma unroll
    for (int i = 0; i < 8; i++) {
        int idx = i * NTH + tid;
        int k = idx >> 5, f4 = (idx & 31) << 2;
        const float* src = Bg + (size_t)(kb + k) * NW + colBase + f4;
        cpa16(sB + (uint32_t)(k * BS_STRIDE + f4) * 4, src, true);
    }
}

// ---------------------------------------------------------------------------
// 64x64 fragment load for one k-step (32 regs).
// ---------------------------------------------------------------------------
template <bool CVTA>
__device__ __forceinline__ void load_frags(
    const float* As, const float* Bs, uint32_t a[4][4], uint32_t b[8][2],
    int ks, int wm, int wn, int gid, int tig)
{
    const uint32_t* Au = (const uint32_t*)As;
    const uint32_t* Bu = (const uint32_t*)Bs;
    const int k = ks * 8 + tig;
#pragma unroll
    for (int mt = 0; mt < 4; mt++) {
        const int m = wm * 64 + mt * 16 + gid;
        if (CVTA) {
            a[mt][0] = f2tf(As[m * AS_STRIDE + k]);
            a[mt][1] = f2tf(As[(m + 8) * AS_STRIDE + k]);
            a[mt][2] = f2tf(As[m * AS_STRIDE + k + 4]);
            a[mt][3] = f2tf(As[(m + 8) * AS_STRIDE + k + 4]);
        } else {
            a[mt][0] = Au[m * AS_STRIDE + k];
            a[mt][1] = Au[(m + 8) * AS_STRIDE + k];
            a[mt][2] = Au[m * AS_STRIDE + k + 4];
            a[mt][3] = Au[(m + 8) * AS_STRIDE + k + 4];
        }
    }
#pragma unroll
    for (int nt = 0; nt < 8; nt++) {
        const int n = wn * 64 + nt * 8 + gid;
        b[nt][0] = Bu[k * BS_STRIDE + n];
        b[nt][1] = Bu[(k + 4) * BS_STRIDE + n];
    }
}

// Warp 64x64 compute on one 32-deep K chunk, fragments double-buffered.
template <bool CVTA>
__device__ __forceinline__ void compute_tile6464(
    const float* As, const float* Bs, float acc[4][8][4],
    int wm, int wn, int gid, int tig)
{
    uint32_t a[2][4][4], b[2][8][2];
    load_frags<CVTA>(As, Bs, a[0], b[0], 0, wm, wn, gid, tig);
#pragma unroll
    for (int ks = 0; ks < 4; ks++) {
        const int cur = ks & 1;
        if (ks < 3)
            load_frags<CVTA>(As, Bs, a[cur ^ 1], b[cur ^ 1], ks + 1, wm, wn, gid, tig);
#pragma unroll
        for (int mt = 0; mt < 4; mt++)
#pragma unroll
            for (int nt = 0; nt < 8; nt++)
                mma_tf32(acc[mt][nt][0], acc[mt][nt][1], acc[mt][nt][2], acc[mt][nt][3],
                         a[cur][mt][0], a[cur][mt][1], a[cur][mt][2], a[cur][mt][3],
                         b[cur][nt][0], b[cur][nt][1]);
    }
}

// 3-stage pipelined mainloop, ONE barrier per chunk, loads issued before
// compute. Safety: the sync at iter kt proves all warps finished chunk kt-1,
// which is what occupies the load-target stage (kt+2)%3.
template <int NW, bool CVTA>
__device__ __forceinline__ void gemm_mainloop(
    char* smem, const float* __restrict__ Ag, const float* __restrict__ Bg,
    int rowBase, int colBase, int E, int tid, float acc[4][8][4],
    int wm, int wn, int gid, int tig)
{
    const uint32_t sb = smem_u32(smem);

#pragma unroll
    for (int mt = 0; mt < 4; mt++)
#pragma unroll
        for (int nt = 0; nt < 8; nt++)
#pragma unroll
            for (int r = 0; r < 4; r++) acc[mt][nt][r] = 0.0f;

    load_tile<NW>(sb, sb + AS_BYTES, Ag, Bg, rowBase, colBase, 0, E, tid);
    CP_COMMIT();
    load_tile<NW>(sb + STAGE_BYTES, sb + STAGE_BYTES + AS_BYTES,
                  Ag, Bg, rowBase, colBase, 32, E, tid);
    CP_COMMIT();

    for (int kt = 0; kt < 16; kt++) {
        CP_WAIT(1);
        __syncthreads();
        if (kt + 2 < 16) {
            uint32_t st = sb + (uint32_t)((kt + 2) % 3) * STAGE_BYTES;
            load_tile<NW>(st, st + AS_BYTES, Ag, Bg, rowBase, colBase,
                          (kt + 2) * 32, E, tid);
        }
        CP_COMMIT();
        const float* As = (const float*)(smem + (kt % 3) * STAGE_BYTES);
        const float* Bs = As + 128 * AS_STRIDE;
        compute_tile6464<CVTA>(As, Bs, acc, wm, wn, gid, tig);
    }
    CP_WAIT(0);
    __syncthreads();
}

// ---------------------------------------------------------------------------
// Big GEMM: C(E x 512) = A @ B(512x512) + bias. CTA 128x128, 128 thr,
// 2 CTA/SM (smem-limited). Grid (4, rb): col block fastest -> A shared via L2.
// ---------------------------------------------------------------------------
template <bool CVTA, bool RELU_ROUND>
__global__ __launch_bounds__(NTH) void gemm_mma(
    const float* __restrict__ Ag, const float* __restrict__ Bg,
    const float* __restrict__ bias, float* __restrict__ C, int E)
{
    extern __shared__ __align__(16) char smem[];
    __shared__ float sbias[128];

    const int tid = threadIdx.x;
    const int wid = tid >> 5, lane = tid & 31;
    const int wm = wid >> 1, wn = wid & 1;       // 2x2 warp grid, warp 64x64
    const int gid = lane >> 2, tig = lane & 3;
    const int rowBase = blockIdx.y * 128;
    const int colBase = blockIdx.x * 128;

    sbias[tid] = bias[colBase + tid];

    float acc[4][8][4];
    gemm_mainloop<D, CVTA>(smem, Ag, Bg, rowBase, colBase, E, tid, acc,
                           wm, wn, gid, tig);

#pragma unroll
    for (int mt = 0; mt < 4; mt++) {
        const int r0 = rowBase + wm * 64 + mt * 16 + gid;
#pragma unroll
        for (int nt = 0; nt < 8; nt++) {
            const int cl = wn * 64 + nt * 8 + tig * 2;
            const int c = colBase + cl;
            float v0 = acc[mt][nt][0] + sbias[cl];
            float v1 = acc[mt][nt][1] + sbias[cl + 1];
            float v2 = acc[mt][nt][2] + sbias[cl];
            float v3 = acc[mt][nt][3] + sbias[cl + 1];
            if (RELU_ROUND) {
                v0 = rna_tf32f(fmaxf(v0, 0.f)); v1 = rna_tf32f(fmaxf(v1, 0.f));
                v2 = rna_tf32f(fmaxf(v2, 0.f)); v3 = rna_tf32f(fmaxf(v3, 0.f));
            }
            if (r0 < E)     *(float2*)&C[(size_t)r0 * D + c]       = make_float2(v0, v1);
            if (r0 + 8 < E) *(float2*)&C[(size_t)(r0 + 8) * D + c] = make_float2(v2, v3);
        }
    }
}

// ---------------------------------------------------------------------------
// Head: T1 = relu(edge @ Wt1 + bt1) (128x128, K=512), same structure, then
// per-row 128->4 GEMV + softmax + gate + small outputs.
// ---------------------------------------------------------------------------
__global__ __launch_bounds__(NTH) void head_mma(
    const float* __restrict__ EE, const float* __restrict__ Wt1,
    const float* __restrict__ bt1, const float* __restrict__ Wt2,
    const float* __restrict__ bt2, float* __restrict__ out, int E)
{
    extern __shared__ __align__(16) char smem[];
    __shared__ float sWt2[512];
    __shared__ float sbt1[128];

    const int tid = threadIdx.x;
    const int wid = tid >> 5, lane = tid & 31;
    const int wm = wid >> 1, wn = wid & 1;
    const int gid = lane >> 2, tig = lane & 3;
    const int rowBase = blockIdx.x * 128;

    sbt1[tid] = bt1[tid];
    sWt2[tid]       = Wt2[tid];
    sWt2[tid + 128] = Wt2[tid + 128];
    sWt2[tid + 256] = Wt2[tid + 256];
    sWt2[tid + 384] = Wt2[tid + 384];

    float acc[4][8][4];
    gemm_mainloop<128, true>(smem, EE, Wt1, rowBase, 0, E, tid, acc,
                             wm, wn, gid, tig);

    // T1 -> padded slab [128][129] (66048 B <= 107520 B smem)
    float* T1 = (float*)smem;
#pragma unroll
    for (int mt = 0; mt < 4; mt++) {
        const int r = wm * 64 + mt * 16 + gid;
#pragma unroll
        for (int nt = 0; nt < 8; nt++) {
            const int c = wn * 64 + nt * 8 + tig * 2;
            T1[r * 129 + c]           = fmaxf(acc[mt][nt][0] + sbt1[c], 0.f);
            T1[r * 129 + c + 1]       = fmaxf(acc[mt][nt][1] + sbt1[c + 1], 0.f);
            T1[(r + 8) * 129 + c]     = fmaxf(acc[mt][nt][2] + sbt1[c], 0.f);
            T1[(r + 8) * 129 + c + 1] = fmaxf(acc[mt][nt][3] + sbt1[c + 1], 0.f);
        }
    }
    __syncthreads();

    // Phase 2: one thread per row (128 threads = 128 rows)
    {
        const int gr = rowBase + tid;
        if (gr < E) {
            float t0 = __ldg(&bt2[0]), t1 = __ldg(&bt2[1]);
            float t2 = __ldg(&bt2[2]), t3 = __ldg(&bt2[3]);
            const float* rp = T1 + tid * 129;
#pragma unroll 8
            for (int k = 0; k < 128; k++) {
                float x = rp[k];
                t0 = fmaf(x, sWt2[k * 4 + 0], t0);
                t1 = fmaf(x, sWt2[k * 4 + 1], t1);
                t2 = fmaf(x, sWt2[k * 4 + 2], t2);
                t3 = fmaf(x, sWt2[k * 4 + 3], t3);
            }
            float m = fmaxf(fmaxf(t0, t1), fmaxf(t2, t3));
            float e0 = __expf(t0 - m), e1 = __expf(t1 - m);
            float e2 = __expf(t2 - m), e3 = __expf(t3 - m);
            float inv = 1.0f / (e0 + e1 + e2 + e3);
            float p0 = e0 * inv, p1 = e1 * inv, p2 = e2 * inv, p3 = e3 * inv;
            float tw0 = 1.0f - p0;

            const size_t Es = (size_t)E;
            out[0 * Es + gr] = tw0;
            out[1 * Es + gr] = p1;
            out[2 * Es + gr] = p2;
            out[3 * Es + gr] = p3;
            float* mw = out + 4 * Es;
            mw[0 * Es + gr] = gatef(tw0);
            mw[1 * Es + gr] = gatef(p1);
            mw[2 * Es + gr] = gatef(p2);
            mw[3 * Es + gr] = gatef(p3);
            float* to = out + 8 * Es;
            to[(size_t)gr * 4 + 0] = p0;
            to[(size_t)gr * 4 + 1] = p1;
            to[(size_t)gr * 4 + 2] = p2;
            to[(size_t)gr * 4 + 3] = p3;
        }
    }
}

// ---------------------------------------------------------------------------
extern "C" void kernel_launch(void* const* d_in, const int* in_sizes, int n_in,
                              void* d_out, int out_size)
{
    const float* pred = (const float*)d_in[1];
    const float* We1  = (const float*)d_in[2];
    const float* be1  = (const float*)d_in[3];
    const float* We2  = (const float*)d_in[4];
    const float* be2  = (const float*)d_in[5];
    const float* Wt1  = (const float*)d_in[6];
    const float* bt1  = (const float*)d_in[7];
    const float* Wt2  = (const float*)d_in[8];
    const float* bt2  = (const float*)d_in[9];

    const int E = in_sizes[1] / D;
    float* out  = (float*)d_out;
    float* edge = out + (size_t)12 * E;

    float *pH, *pW1r, *pW2r, *pWt1r;
    cudaGetSymbolAddress((void**)&pH,   g_h);
    cudaGetSymbolAddress((void**)&pW1r, g_W1r);
    cudaGetSymbolAddress((void**)&pW2r, g_W2r);
    cudaGetSymbolAddress((void**)&pWt1r, g_Wt1r);

    cudaFuncSetAttribute(gemm_mma<true, true>,
                         cudaFuncAttributeMaxDynamicSharedMemorySize, SMEM_TOTAL);
    cudaFuncSetAttribute(gemm_mma<false, false>,
                         cudaFuncAttributeMaxDynamicSharedMemorySize, SMEM_TOTAL);
    cudaFuncSetAttribute(head_mma,
                         cudaFuncAttributeMaxDynamicSharedMemorySize, SMEM_TOTAL);

    round_weights<<<(147456 + 255) / 256, 256>>>(
        (const float4*)We1, (const float4*)We2, (const float4*)Wt1,
        (float4*)pW1r, (float4*)pW2r, (float4*)pWt1r);

    const int rb = (E + 127) / 128;
    dim3 grid(4, rb);   // col block fastest -> A shared via L2

    gemm_mma<true,  true ><<<grid, NTH, SMEM_TOTAL>>>(pred, pW1r, be1, pH, E);
    gemm_mma<false, false><<<grid, NTH, SMEM_TOTAL>>>(pH,   pW2r, be2, edge, E);
    head_mma<<<rb, NTH, SMEM_TOTAL>>>(edge, pWt1r, bt1, Wt2, bt2, out, E);
}